// round 8
// baseline (speedup 1.0000x reference)
#include <cuda_runtime.h>
#include <cuda_fp16.h>
#include <cstdint>

#define BATCH 16
#define SEQ   4096
#define NST   256
#define TAPS  8
#define PAD   8
#define RPB   (SEQ + PAD)          // 4104 padded rows per batch
#define NCHUNK 32                  // 8 taps * 4 K-chunks of 64
#define GSC   65536.0f
#define GINV  (1.0f/65536.0f)

// SMEM: A/B tiles 128 rows x 64 halves, row stride padded to 144B
#define ROWB   144
#define TILEB  (128 * ROWB)        // 18432
#define SM_A0  0
#define SM_B0  TILEB
#define SM_A1  (2 * TILEB)
#define SM_B1  (3 * TILEB)
#define SMEM_SZ (4 * TILEB)        // 73728

// ---------------- device scratch (no allocs allowed) ----------------
__device__ __align__(16) __half g_xh[(size_t)BATCH * RPB * NST];
__device__ float g_A2[NST*NST], g_A4[NST*NST];
__device__ float g_P[7][NST*NST];                   // g_P[k-1] = A^k B
__device__ __align__(16) __half g_G[TAPS][NST*NST]; // G_k = C A^k B * 2^16

__device__ __forceinline__ uint32_t smem_u32(const void* p) {
    uint32_t a;
    asm("{ .reg .u64 t; cvta.to.shared.u64 t, %1; cvt.u32.u64 %0, t; }" : "=r"(a) : "l"(p));
    return a;
}

// ============ kernel 1: x fp32 -> fp16, zero-padded windows ============
__global__ void k_convert(const float* __restrict__ x) {
    int bb = blockIdx.y;
    int r  = blockIdx.x * 8 + (threadIdx.x >> 5);
    int c  = (threadIdx.x & 31) * 8;
    __half* dst = g_xh + ((size_t)bb * RPB + r) * NST + c;
    if (r < PAD) {
        *reinterpret_cast<uint4*>(dst) = make_uint4(0, 0, 0, 0);
    } else {
        const float4* src = reinterpret_cast<const float4*>(
            x + ((size_t)bb * SEQ + (r - PAD)) * NST + c);
        float4 v0 = src[0], v1 = src[1];
        __half2 h[4];
        h[0] = __floats2half2_rn(v0.x, v0.y); h[1] = __floats2half2_rn(v0.z, v0.w);
        h[2] = __floats2half2_rn(v1.x, v1.y); h[3] = __floats2half2_rn(v1.z, v1.w);
        *reinterpret_cast<uint4*>(dst) = *reinterpret_cast<uint4*>(h);
    }
}

// ============ precompute: G_k = C A^k B via log-doubling ============
__device__ void mm_tile(const float* __restrict__ X, const float* __restrict__ Y,
                        float* Of, __half* Oh) {
    __shared__ float xs[16][68], ys[16][68];
    int tid = threadIdx.x, tx = tid & 15, ty = tid >> 4;
    int r0 = blockIdx.y * 64, c0 = blockIdx.x * 64;
    float acc[4][4] = {};
    for (int k0 = 0; k0 < NST; k0 += 16) {
#pragma unroll
        for (int q = 0; q < 4; q++) {
            int idx = tid + 256 * q;
            xs[idx & 15][idx >> 4] = X[(r0 + (idx >> 4)) * NST + k0 + (idx & 15)];
            ys[idx >> 6][idx & 63] = Y[(k0 + (idx >> 6)) * NST + c0 + (idx & 63)];
        }
        __syncthreads();
#pragma unroll
        for (int kk = 0; kk < 16; kk++) {
            float a[4], b[4];
#pragma unroll
            for (int i = 0; i < 4; i++) a[i] = xs[kk][ty * 4 + i];
#pragma unroll
            for (int j = 0; j < 4; j++) b[j] = ys[kk][tx * 4 + j];
#pragma unroll
            for (int i = 0; i < 4; i++)
#pragma unroll
                for (int j = 0; j < 4; j++) acc[i][j] += a[i] * b[j];
        }
        __syncthreads();
    }
#pragma unroll
    for (int i = 0; i < 4; i++)
#pragma unroll
        for (int j = 0; j < 4; j++) {
            int o = (r0 + ty * 4 + i) * NST + c0 + tx * 4 + j;
            if (Of) Of[o] = acc[i][j];
            else    Oh[o] = __float2half_rn(acc[i][j] * GSC);
        }
}

__global__ void k_mm(const float* __restrict__ A, const float* __restrict__ B,
                     const float* __restrict__ C, int stage) {
    int z = blockIdx.z;
    const float *X, *Y; float* Of = nullptr; __half* Oh = nullptr;
    if (stage == 1) {
        if (z == 0) { X = A; Y = A; Of = g_A2; } else { X = A; Y = B; Of = g_P[0]; }
    } else if (stage == 2) {
        if (z == 0)      { X = g_A2; Y = g_A2;   Of = g_A4;  }
        else if (z == 1) { X = g_A2; Y = B;      Of = g_P[1]; }
        else             { X = g_A2; Y = g_P[0]; Of = g_P[2]; }
    } else if (stage == 3) {
        X = g_A4; Y = (z == 0) ? B : g_P[z - 1]; Of = g_P[z + 3];
    } else {
        X = C; Y = (z == 0) ? B : g_P[z - 1]; Oh = g_G[z];
    }
    mm_tile(X, Y, Of, Oh);
}

// ============ main: out = (Σ_k G_k x_{t-k}) * 2^-16 + D⊙x ============
// CTA: M=128 (t rows), N=128 (out cols), K=2048 via 32 chunks of 64.
// 8 warps = 4(M) x 2(N); warp tile 32x64; mma.sync.m16n8k16 f16->f32.
__global__ void __launch_bounds__(256) k_main(const float* __restrict__ x,
                                              const float* __restrict__ Dv,
                                              float* __restrict__ out) {
    extern __shared__ char smem[];
    const uint32_t sb = smem_u32(smem);
    int tid = threadIdx.x, lane = tid & 31, wid = tid >> 5;
    int bx = blockIdx.x;
    int nh = bx & 1, tt = (bx >> 1) & 31, b = bx >> 6;
    int t0 = tt * 128, m0 = nh * 128;
    int warp_m = wid >> 1, warp_n = wid & 1;

    const __half* xb = g_xh + (size_t)b * RPB * NST;
    const uint32_t SA[2] = { sb + SM_A0, sb + SM_A1 };
    const uint32_t SB[2] = { sb + SM_B0, sb + SM_B1 };

    auto load_chunk = [&](int c, int bu) {
        int k = c >> 2, n0 = (c & 3) * 64;
        const char* asrc = (const char*)(xb + (size_t)(t0 + PAD - k) * NST + n0);
        const char* bsrc = (const char*)(g_G[k] + (size_t)m0 * NST + n0);
#pragma unroll
        for (int q = 0; q < 4; q++) {
            int idx = tid + 256 * q;
            int r = idx >> 3, g = idx & 7;
            uint32_t ao = SA[bu] + r * ROWB + g * 16;
            uint32_t bo = SB[bu] + r * ROWB + g * 16;
            asm volatile("cp.async.cg.shared.global [%0], [%1], 16;"
                         :: "r"(ao), "l"(asrc + (size_t)r * NST * 2 + g * 16) : "memory");
            asm volatile("cp.async.cg.shared.global [%0], [%1], 16;"
                         :: "r"(bo), "l"(bsrc + (size_t)r * NST * 2 + g * 16) : "memory");
        }
        asm volatile("cp.async.commit_group;" ::: "memory");
    };

    float acc[2][8][4];
#pragma unroll
    for (int i = 0; i < 2; i++)
#pragma unroll
        for (int j = 0; j < 8; j++)
#pragma unroll
            for (int q = 0; q < 4; q++) acc[i][j][q] = 0.0f;

    load_chunk(0, 0);

    for (int i = 0; i < NCHUNK; i++) {
        if (i + 1 < NCHUNK) {
            load_chunk(i + 1, (i + 1) & 1);
            asm volatile("cp.async.wait_group 1;" ::: "memory");
        } else {
            asm volatile("cp.async.wait_group 0;" ::: "memory");
        }
        __syncthreads();
        uint32_t Ab = SA[i & 1], Bb = SB[i & 1];
#pragma unroll
        for (int kk = 0; kk < 4; kk++) {
            uint32_t kcol = (kk * 16 + (lane >> 4) * 8) * 2;  // bytes
            uint32_t a[2][4];
#pragma unroll
            for (int fm = 0; fm < 2; fm++) {
                uint32_t addr = Ab + (warp_m * 32 + fm * 16 + (lane & 15)) * ROWB + kcol;
                asm volatile("ldmatrix.sync.aligned.m8n8.x4.shared.b16 {%0,%1,%2,%3}, [%4];"
                    : "=r"(a[fm][0]), "=r"(a[fm][1]), "=r"(a[fm][2]), "=r"(a[fm][3])
                    : "r"(addr));
            }
            uint32_t bf[8][2];
#pragma unroll
            for (int fp = 0; fp < 4; fp++) {
                uint32_t addr = Bb + (warp_n * 64 + fp * 16 + (lane & 15)) * ROWB + kcol;
                uint32_t r0, r1, r2, r3;
                asm volatile("ldmatrix.sync.aligned.m8n8.x4.shared.b16 {%0,%1,%2,%3}, [%4];"
                    : "=r"(r0), "=r"(r1), "=r"(r2), "=r"(r3) : "r"(addr));
                bf[2 * fp][0] = r0; bf[2 * fp][1] = r2;
                bf[2 * fp + 1][0] = r1; bf[2 * fp + 1][1] = r3;
            }
#pragma unroll
            for (int fm = 0; fm < 2; fm++)
#pragma unroll
                for (int fn = 0; fn < 8; fn++)
                    asm volatile(
                        "mma.sync.aligned.m16n8k16.row.col.f32.f16.f16.f32 "
                        "{%0,%1,%2,%3}, {%4,%5,%6,%7}, {%8,%9}, {%0,%1,%2,%3};"
                        : "+f"(acc[fm][fn][0]), "+f"(acc[fm][fn][1]),
                          "+f"(acc[fm][fn][2]), "+f"(acc[fm][fn][3])
                        : "r"(a[fm][0]), "r"(a[fm][1]), "r"(a[fm][2]), "r"(a[fm][3]),
                          "r"(bf[fn][0]), "r"(bf[fn][1]));
        }
        __syncthreads();
    }

    // epilogue: acc frag (fm,fn): rows qr,(qr+8), cols 2*qc,+1
    int qr = lane >> 2, qc = lane & 3;
#pragma unroll
    for (int fm = 0; fm < 2; fm++) {
#pragma unroll
        for (int hh = 0; hh < 2; hh++) {
            int t = t0 + warp_m * 32 + fm * 16 + qr + hh * 8;
            const float* xrow = x + ((size_t)b * SEQ + t) * NST;
            float* orow = out + ((size_t)b * SEQ + t) * NST;
#pragma unroll
            for (int fn = 0; fn < 8; fn++) {
                int c = m0 + warp_n * 64 + fn * 8 + qc * 2;
                float2 xv = *reinterpret_cast<const float2*>(xrow + c);
                float d0 = __ldg(Dv + c), d1 = __ldg(Dv + c + 1);
                float2 o;
                o.x = acc[fm][fn][hh * 2 + 0] * GINV + d0 * xv.x;
                o.y = acc[fm][fn][hh * 2 + 1] * GINV + d1 * xv.y;
                *reinterpret_cast<float2*>(orow + c) = o;
            }
        }
    }
}

// ============ launch ============
extern "C" void kernel_launch(void* const* d_in, const int* in_sizes, int n_in,
                              void* d_out, int out_size) {
    const float* x  = (const float*)d_in[0];
    const float* A  = (const float*)d_in[1];
    const float* B  = (const float*)d_in[2];
    const float* C  = (const float*)d_in[3];
    const float* Dv = (const float*)d_in[4];
    float* out = (float*)d_out;

    cudaFuncSetAttribute(k_main, cudaFuncAttributeMaxDynamicSharedMemorySize, SMEM_SZ);

    k_convert<<<dim3(RPB / 8, BATCH), 256>>>(x);
    k_mm<<<dim3(4, 4, 2), 256>>>(A, B, C, 1);   // A2, P1
    k_mm<<<dim3(4, 4, 3), 256>>>(A, B, C, 2);   // A4, P2, P3
    k_mm<<<dim3(4, 4, 4), 256>>>(A, B, C, 3);   // P4..P7
    k_mm<<<dim3(4, 4, 8), 256>>>(A, B, C, 4);   // G0..G7 (fp16, x2^16)
    k_main<<<1024, 256, SMEM_SZ>>>(x, Dv, out);
}